// round 7
// baseline (speedup 1.0000x reference)
#include <cuda_runtime.h>

// DeformConv3d, dimension='HW': t-offset == 0 -> pure 2D bilinear at integer t.
// R7 = R5/R6 structure (c4 channels-last gathers, kt 3-split, f32x2 GEMM,
// weight-LDS amortization) with G=2 h-rows per thread instead of 4, and
// __launch_bounds__(192,3): regs <=113 -> 3 blocks/SM -> occupancy 15.8->28%.
// Latency-limited regime (issue 20%, no pipe >63%): buy warps with registers.

#define NB  2
#define NC  16
#define NT  8
#define NH  64
#define NW  64
#define NCO 16
#define NK  27
#define HW  (NH * NW)     // 4096
#define THW (NT * HW)     // 32768

#define FMA2(d, a, b) \
    asm("fma.rn.f32x2 %0, %1, %2, %0;" : "+l"(d) : "l"(a), "l"(b))
#define PACK2(d, lo, hi) \
    asm("mov.b64 %0, {%1, %2};" : "=l"(d) : "f"(lo), "f"(hi))
#define PACKB(d, s) \
    asm("mov.b64 %0, {%1, %1};" : "=l"(d) : "f"(s))
#define UNPACK2(lo, hi, s) \
    asm("mov.b64 {%0, %1}, %2;" : "=f"(lo), "=f"(hi) : "l"(s))

// x in c4-grouped channels-last layout: [b][t][g][hw] of float4 (c = 4g+j)
__device__ __align__(16) float g_x4[NB * NT * 4 * HW * 4];

__global__ void transpose_x_kernel(const float* __restrict__ x)
{
    const int tid = blockIdx.x * blockDim.x + threadIdx.x;  // 0 .. 262143
    const int hw = tid & (HW - 1);
    const int g  = (tid >> 12) & 3;
    const int t  = (tid >> 14) & 7;
    const int b  = tid >> 17;
    float4 v;
    v.x = x[((b * NC + 4 * g + 0) * NT + t) * HW + hw];
    v.y = x[((b * NC + 4 * g + 1) * NT + t) * HW + hw];
    v.z = x[((b * NC + 4 * g + 2) * NT + t) * HW + hw];
    v.w = x[((b * NC + 4 * g + 3) * NT + t) * HW + hw];
    reinterpret_cast<float4*>(g_x4)[tid] = v;
}

// ---------------------------------------------------------------------------
// Block = 192 threads = 3 kt-parts x 64 lanes (lane = w). Each thread computes
// points (hb+j, w), j = 0..1. Block covers (b, t, 2 h-rows) = 128 points.
// Grid = 2*8*32 = 512 blocks.
#define TPB 192

__global__ void __launch_bounds__(TPB, 3)
deform_conv3d_hw_kernel(const float* __restrict__ temp,
                        const float* __restrict__ wgt,
                        const float* __restrict__ bias,
                        float* __restrict__ out)
{
    // weights as [k][c][co]: 16 contiguous co per (k,c) -> LDS.128 broadcast
    __shared__ __align__(16) float wsm[NK * NC * NCO];                // 27648 B
    __shared__ __align__(16) unsigned long long redsm[2][64][2][8];   // 16384 B

    for (int i = threadIdx.x; i < NK * NC * NCO; i += TPB) {
        int co = i & 15;
        int c  = (i >> 4) & 15;
        int k  = i >> 8;
        wsm[i] = wgt[(co * NC + c) * NK + k];
    }

    const int part = threadIdx.x / 64;          // warp-coherent
    const int w    = threadIdx.x & 63;          // lane = w
    const int bid  = blockIdx.x;                // b*256 + t*32 + hgrp
    const int hb = (bid & 31) << 1;             // base of 2 h-rows
    const int t  = (bid >> 5) & 7;
    const int b  = bid >> 8;

    unsigned long long acc[2][8];
    if (part == 0) {
#pragma unroll
        for (int j = 0; j < 2; j++)
#pragma unroll
            for (int m = 0; m < 8; m++)
                PACK2(acc[j][m], bias[2 * m], bias[2 * m + 1]);
    } else {
#pragma unroll
        for (int j = 0; j < 2; j++)
#pragma unroll
            for (int m = 0; m < 8; m++) acc[j][m] = 0ULL;
    }

    __syncthreads();   // wsm ready

    const int ti = t - 1 + part;
    if (ti >= 0 && ti < NT) {
        const ulonglong2* __restrict__ x4base =
            reinterpret_cast<const ulonglong2*>(g_x4) + (b * NT + ti) * 4 * HW;
        const float* __restrict__ tb =
            temp + b * (2 * NK * THW) + t * HW + hb * NW + w;
        const int kbase = part * 9;

#pragma unroll
        for (int kk = 0; kk < 9; kk++) {
            const int kh = kk / 3;
            const int kw = kk - kh * 3;
            const int k  = kbase + kk;

            float ccf[2][4];
            int   idx[2][4];
#pragma unroll
            for (int j = 0; j < 2; j++) {
                const int h = hb + j;
                const float offh = __ldg(tb + (2 * k) * THW + j * NW);
                const float offw = __ldg(tb + (2 * k + 1) * THW + j * NW);

                const float ph = (float)(h - 1 + kh) + offh;
                const float pw = (float)(w - 1 + kw) + offw;

                const int h0 = __float2int_rd(ph);
                const int w0 = __float2int_rd(pw);
                const float fh = ph - (float)h0;
                const float fw = pw - (float)w0;
                const int h1 = h0 + 1;
                const int w1 = w0 + 1;

                const bool vh0 = (h0 >= 0) & (h0 < NH);
                const bool vh1 = (h1 >= 0) & (h1 < NH);
                const bool vw0 = (w0 >= 0) & (w0 < NW);
                const bool vw1 = (w1 >= 0) & (w1 < NW);

                const float gh0 = 1.0f - fh, gw0 = 1.0f - fw;
                ccf[j][0] = (vh0 & vw0) ? gh0 * gw0 : 0.0f;
                ccf[j][1] = (vh0 & vw1) ? gh0 * fw  : 0.0f;
                ccf[j][2] = (vh1 & vw0) ? fh  * gw0 : 0.0f;
                ccf[j][3] = (vh1 & vw1) ? fh  * fw  : 0.0f;

                const int h0c = min(max(h0, 0), NH - 1);
                const int h1c = min(max(h1, 0), NH - 1);
                const int w0c = min(max(w0, 0), NW - 1);
                const int w1c = min(max(w1, 0), NW - 1);
                idx[j][0] = h0c * NW + w0c;
                idx[j][1] = h0c * NW + w1c;
                idx[j][2] = h1c * NW + w0c;
                idx[j][3] = h1c * NW + w1c;
            }

#pragma unroll
            for (int g = 0; g < 4; g++) {
                const ulonglong2* __restrict__ pg = x4base + g * HW;

                // bilinear values for 2 points: u[j] packs channels
                // {4g,4g+1} (lo) and {4g+2,4g+3} (hi)
                unsigned long long u[2][2];
#pragma unroll
                for (int j = 0; j < 2; j++) {
                    u[j][0] = 0ULL; u[j][1] = 0ULL;
#pragma unroll
                    for (int q = 0; q < 4; q++) {
                        unsigned long long cc;
                        PACKB(cc, ccf[j][q]);
                        const ulonglong2 a = __ldg(pg + idx[j][q]);
                        FMA2(u[j][0], cc, a.x);
                        FMA2(u[j][1], cc, a.y);
                    }
                }

                // GEMM: weights for channels 4g..4g+3, loaded once, used 2x
                const ulonglong2* __restrict__ wr =
                    (const ulonglong2*)(wsm + (k * NC + 4 * g) * NCO);
#pragma unroll
                for (int cp = 0; cp < 2; cp++) {
                    const ulonglong2 q0 = wr[cp * 8 + 0];
                    const ulonglong2 q1 = wr[cp * 8 + 1];
                    const ulonglong2 q2 = wr[cp * 8 + 2];
                    const ulonglong2 q3 = wr[cp * 8 + 3];
                    const ulonglong2 r0 = wr[cp * 8 + 4];
                    const ulonglong2 r1 = wr[cp * 8 + 5];
                    const ulonglong2 r2 = wr[cp * 8 + 6];
                    const ulonglong2 r3 = wr[cp * 8 + 7];
#pragma unroll
                    for (int j = 0; j < 2; j++) {
                        float v0, v1;
                        UNPACK2(v0, v1, u[j][cp]);
                        unsigned long long vv0, vv1;
                        PACKB(vv0, v0);
                        PACKB(vv1, v1);
                        FMA2(acc[j][0], vv0, q0.x); FMA2(acc[j][1], vv0, q0.y);
                        FMA2(acc[j][2], vv0, q1.x); FMA2(acc[j][3], vv0, q1.y);
                        FMA2(acc[j][4], vv0, q2.x); FMA2(acc[j][5], vv0, q2.y);
                        FMA2(acc[j][6], vv0, q3.x); FMA2(acc[j][7], vv0, q3.y);
                        FMA2(acc[j][0], vv1, r0.x); FMA2(acc[j][1], vv1, r0.y);
                        FMA2(acc[j][2], vv1, r1.x); FMA2(acc[j][3], vv1, r1.y);
                        FMA2(acc[j][4], vv1, r2.x); FMA2(acc[j][5], vv1, r2.y);
                        FMA2(acc[j][6], vv1, r3.x); FMA2(acc[j][7], vv1, r3.y);
                    }
                }
            }
        }
    }

    // reduce parts 1,2 into part 0 through smem (single wave, G=2 fits)
    if (part > 0) {
#pragma unroll
        for (int j = 0; j < 2; j++)
#pragma unroll
            for (int m = 0; m < 8; m++)
                redsm[part - 1][w][j][m] = acc[j][m];
    }
    __syncthreads();

    if (part == 0) {
#pragma unroll
        for (int j = 0; j < 2; j++) {
            float* ob = out + b * (NCO * THW) + t * HW + (hb + j) * NW + w;
#pragma unroll
            for (int m = 0; m < 8; m++) {
                float a0, a1, p0, p1, q0, q1;
                UNPACK2(a0, a1, acc[j][m]);
                UNPACK2(p0, p1, redsm[0][w][j][m]);
                UNPACK2(q0, q1, redsm[1][w][j][m]);
                ob[(2 * m) * THW]     = a0 + p0 + q0;
                ob[(2 * m + 1) * THW] = a1 + p1 + q1;
            }
        }
    }
}

extern "C" void kernel_launch(void* const* d_in, const int* in_sizes, int n_in,
                              void* d_out, int out_size)
{
    const float* x    = (const float*)d_in[0];
    const float* temp = (const float*)d_in[1];
    const float* wgt  = (const float*)d_in[2];
    const float* bias = (const float*)d_in[3];
    float* out = (float*)d_out;

    transpose_x_kernel<<<(NB * NT * 4 * HW) / 256, 256>>>(x);

    deform_conv3d_hw_kernel<<<512, TPB>>>(temp, wgt, bias, out);
}

// round 9
// speedup vs baseline: 1.7408x; 1.7408x over previous
#include <cuda_runtime.h>
#include <cuda_bf16.h>
#include <cstdint>

// DeformConv3d 'HW' (t-offset == 0 -> 2D bilinear at integer t).
// R9: co-GEMM on warp-level HMMA (mma.sync.m16n8k16 bf16, sm_80+ baseline ->
// compiles for plain sm_103). bf16 hi/lo split, 3 MMA terms, fp32 accumulate.
// Warp = 32 consecutive output points; warp-private smem staging; B fragments
// pre-packed in exact mma fragment layout by a prep kernel.

#define NB  2
#define NC  16
#define NT  8
#define NH  64
#define NW  64
#define NCO 16
#define NK  27
#define HW  (NH * NW)
#define THW (NT * HW)

#define FMA2(d, a, b) \
    asm("fma.rn.f32x2 %0, %1, %2, %0;" : "+l"(d) : "l"(a), "l"(b))
#define PACKB(d, s) \
    asm("mov.b64 %0, {%1, %1};" : "=l"(d) : "f"(s))
#define UNPACK2(lo, hi, s) \
    asm("mov.b64 {%0, %1}, %2;" : "=f"(lo), "=f"(hi) : "l"(s))

#define MMA16816(D, A, B) \
    asm volatile("mma.sync.aligned.m16n8k16.row.col.f32.bf16.bf16.f32 " \
        "{%0,%1,%2,%3}, {%4,%5,%6,%7}, {%8,%9}, {%0,%1,%2,%3};" \
        : "+f"((D)[0]), "+f"((D)[1]), "+f"((D)[2]), "+f"((D)[3]) \
        : "r"((A)[0]), "r"((A)[1]), "r"((A)[2]), "r"((A)[3]), \
          "r"((B).x), "r"((B).y))

#define LDM4(R, ADDR) \
    asm volatile("ldmatrix.sync.aligned.m8n8.x4.shared.b16 {%0,%1,%2,%3}, [%4];" \
        : "=r"((R)[0]), "=r"((R)[1]), "=r"((R)[2]), "=r"((R)[3]) : "r"(ADDR))

static __device__ __forceinline__ uint32_t smem_u32(const void* p) {
    uint32_t a;
    asm("{ .reg .u64 t; cvta.to.shared.u64 t, %1; cvt.u32.u64 %0, t; }"
        : "=r"(a) : "l"(p));
    return a;
}

// ---------------------------------------------------------------------------
// scratch
__device__ __align__(16) float g_x4[NB * NT * 4 * HW * 4]; // c4 channels-last x
__device__ __align__(16) uint2 g_bfrag[NK * 2 * 2 * 32];   // B mma fragments

__global__ void transpose_x_kernel(const float* __restrict__ x)
{
    const int tid = blockIdx.x * blockDim.x + threadIdx.x;
    const int hw = tid & (HW - 1);
    const int g  = (tid >> 12) & 3;
    const int t  = (tid >> 14) & 7;
    const int b  = tid >> 17;
    float4 v;
    v.x = x[((b * NC + 4 * g + 0) * NT + t) * HW + hw];
    v.y = x[((b * NC + 4 * g + 1) * NT + t) * HW + hw];
    v.z = x[((b * NC + 4 * g + 2) * NT + t) * HW + hw];
    v.w = x[((b * NC + 4 * g + 3) * NT + t) * HW + hw];
    reinterpret_cast<float4*>(g_x4)[tid] = v;
}

// B fragment pack: mma m16n8k16 B frag, lane l holds
//   b.x = { B[2(l%4)][n], B[2(l%4)+1][n] },  b.y = { B[+8][n], B[+9][n] },
// n = ntile*8 + l/4, k-dim = channel c, B[c][co] = w[co][c][tap].
// layout g_bfrag[tap][split(hi=0,lo=1)][ntile][lane]
__global__ void prep_b_kernel(const float* __restrict__ wgt)
{
    const int i = blockIdx.x * blockDim.x + threadIdx.x;
    if (i >= NK * 2 * 2 * 32) return;
    const int l  = i & 31;
    const int nt = (i >> 5) & 1;
    const int s  = (i >> 6) & 1;
    const int k  = i >> 7;
    const int n  = nt * 8 + (l >> 2);
    const int kp = (l & 3) * 2;

    __nv_bfloat16 e[4];
#pragma unroll
    for (int j = 0; j < 4; j++) {
        const int c = kp + (j & 1) + (j >> 1) * 8;
        const float v = wgt[(n * NC + c) * NK + k];
        const __nv_bfloat16 hi = __float2bfloat16(v);
        e[j] = s ? __float2bfloat16(v - __bfloat162float(hi)) : hi;
    }
    __nv_bfloat162 r0 = __halves2bfloat162(e[0], e[1]);  // .x = low = even c
    __nv_bfloat162 r1 = __halves2bfloat162(e[2], e[3]);
    uint2 o;
    o.x = *reinterpret_cast<uint32_t*>(&r0);
    o.y = *reinterpret_cast<uint32_t*>(&r1);
    g_bfrag[i] = o;
}

// ---------------------------------------------------------------------------
// main kernel: 256 threads = 8 warps, warp = 32 consecutive points.
__global__ void __launch_bounds__(256, 2)
deform_conv3d_mma_kernel(const float* __restrict__ temp,
                         const float* __restrict__ bias,
                         float* __restrict__ out)
{
    __shared__ __align__(16) uint2   bsm[NK * 2 * 2 * 32];   // 27648 B
    __shared__ __align__(16) uint8_t astg[8][2560];          // 20480 B

    const int tid = threadIdx.x;
    for (int i = tid; i < (NK * 2 * 2 * 32) / 2; i += 256)
        reinterpret_cast<uint4*>(bsm)[i] =
            reinterpret_cast<const uint4*>(g_bfrag)[i];
    __syncthreads();

    const int lane = tid & 31;
    const int wid  = tid >> 5;
    const int wpt  = blockIdx.x * 256 + wid * 32;  // warp base point
    const int pt   = wpt + lane;
    const int w = pt & 63;
    const int h = (pt >> 6) & 63;
    const int t = (pt >> 12) & 7;   // warp-uniform
    const int b = pt >> 15;         // warp-uniform
    const int sp = pt & (THW - 1);

    const uint32_t abase = smem_u32(&astg[wid][0]);
    const float* __restrict__ tb = temp + b * (2 * NK * THW) + sp;
    const ulonglong2* __restrict__ x4all =
        reinterpret_cast<const ulonglong2*>(g_x4) + b * NT * 4 * HW;

    float d[2][2][4];
#pragma unroll
    for (int m = 0; m < 2; m++)
#pragma unroll
        for (int n = 0; n < 2; n++)
#pragma unroll
            for (int j = 0; j < 4; j++) d[m][n][j] = 0.0f;

    for (int kt = 0; kt < 3; kt++) {
        const int ti = t - 1 + kt;
        if (ti < 0 || ti >= NT) continue;            // warp-uniform branch
        const ulonglong2* __restrict__ pl = x4all + ti * 4 * HW;

        for (int kk = 0; kk < 9; kk++) {
            const int k  = kt * 9 + kk;
            const int kh = kk / 3;
            const int kw = kk - kh * 3;

            const float offh = __ldg(tb + (2 * k) * THW);
            const float offw = __ldg(tb + (2 * k + 1) * THW);

            const float ph = (float)(h - 1 + kh) + offh;
            const float pw = (float)(w - 1 + kw) + offw;
            const int h0 = __float2int_rd(ph);
            const int w0 = __float2int_rd(pw);
            const float fh = ph - (float)h0;
            const float fw = pw - (float)w0;
            const int h1 = h0 + 1, w1 = w0 + 1;
            const bool vh0 = (h0 >= 0) & (h0 < NH);
            const bool vh1 = (h1 >= 0) & (h1 < NH);
            const bool vw0 = (w0 >= 0) & (w0 < NW);
            const bool vw1 = (w1 >= 0) & (w1 < NW);
            const float gh0 = 1.0f - fh, gw0 = 1.0f - fw;
            const float c00 = (vh0 & vw0) ? gh0 * gw0 : 0.0f;
            const float c01 = (vh0 & vw1) ? gh0 * fw  : 0.0f;
            const float c10 = (vh1 & vw0) ? fh  * gw0 : 0.0f;
            const float c11 = (vh1 & vw1) ? fh  * fw  : 0.0f;
            const int h0c = min(max(h0, 0), NH - 1);
            const int h1c = min(max(h1, 0), NH - 1);
            const int w0c = min(max(w0, 0), NW - 1);
            const int w1c = min(max(w1, 0), NW - 1);
            const int i00 = h0c * NW + w0c;
            const int i01 = h0c * NW + w1c;
            const int i10 = h1c * NW + w0c;
            const int i11 = h1c * NW + w1c;

            unsigned long long cc00, cc01, cc10, cc11;
            PACKB(cc00, c00); PACKB(cc01, c01);
            PACKB(cc10, c10); PACKB(cc11, c11);

            uint32_t hi[8], lo[8];
#pragma unroll
            for (int g = 0; g < 4; g++) {
                const ulonglong2* __restrict__ pg = pl + g * HW;
                unsigned long long u0 = 0ULL, u1 = 0ULL;
                { const ulonglong2 a = __ldg(pg + i00);
                  FMA2(u0, cc00, a.x); FMA2(u1, cc00, a.y); }
                { const ulonglong2 a = __ldg(pg + i01);
                  FMA2(u0, cc01, a.x); FMA2(u1, cc01, a.y); }
                { const ulonglong2 a = __ldg(pg + i10);
                  FMA2(u0, cc10, a.x); FMA2(u1, cc10, a.y); }
                { const ulonglong2 a = __ldg(pg + i11);
                  FMA2(u0, cc11, a.x); FMA2(u1, cc11, a.y); }
                float v0, v1, v2, v3;
                UNPACK2(v0, v1, u0);
                UNPACK2(v2, v3, u1);
                __nv_bfloat162 hA = __floats2bfloat162_rn(v0, v1); // .x = even c
                __nv_bfloat162 hB = __floats2bfloat162_rn(v2, v3);
                float2 fA = __bfloat1622float2(hA);
                float2 fB = __bfloat1622float2(hB);
                __nv_bfloat162 lA = __floats2bfloat162_rn(v0 - fA.x, v1 - fA.y);
                __nv_bfloat162 lB = __floats2bfloat162_rn(v2 - fB.x, v3 - fB.y);
                hi[2 * g]     = *reinterpret_cast<uint32_t*>(&hA);
                hi[2 * g + 1] = *reinterpret_cast<uint32_t*>(&hB);
                lo[2 * g]     = *reinterpret_cast<uint32_t*>(&lA);
                lo[2 * g + 1] = *reinterpret_cast<uint32_t*>(&lB);
            }

            // stage A: row = lane (point), 80B stride; hi at +0..31, lo +32..63
            __syncwarp();
            {
                const uint32_t r = abase + (uint32_t)lane * 80;
                asm volatile("st.shared.v4.b32 [%0], {%1,%2,%3,%4};"
                    :: "r"(r), "r"(hi[0]), "r"(hi[1]), "r"(hi[2]), "r"(hi[3]) : "memory");
                asm volatile("st.shared.v4.b32 [%0], {%1,%2,%3,%4};"
                    :: "r"(r + 16), "r"(hi[4]), "r"(hi[5]), "r"(hi[6]), "r"(hi[7]) : "memory");
                asm volatile("st.shared.v4.b32 [%0], {%1,%2,%3,%4};"
                    :: "r"(r + 32), "r"(lo[0]), "r"(lo[1]), "r"(lo[2]), "r"(lo[3]) : "memory");
                asm volatile("st.shared.v4.b32 [%0], {%1,%2,%3,%4};"
                    :: "r"(r + 48), "r"(lo[4]), "r"(lo[5]), "r"(lo[6]), "r"(lo[7]) : "memory");
            }
            __syncwarp();

            // A fragments: m-tile rows 16m + (lane&15), k-half chunk (lane>>4)*16
            uint32_t ah[2][4], al[2][4];
            {
                const uint32_t r0a = abase + (uint32_t)(lane & 15) * 80
                                   + (uint32_t)(lane >> 4) * 16;
                LDM4(ah[0], r0a);
                LDM4(ah[1], r0a + 16 * 80);
                LDM4(al[0], r0a + 32);
                LDM4(al[1], r0a + 16 * 80 + 32);
            }

            // B fragments (pre-packed): [k][s][nt][lane], uint2 units
            const uint2* __restrict__ bp = bsm + k * 128 + lane;
            const uint2 bh0 = bp[0];
            const uint2 bh1 = bp[32];
            const uint2 bl0 = bp[64];
            const uint2 bl1 = bp[96];

            MMA16816(d[0][0], ah[0], bh0); MMA16816(d[0][1], ah[0], bh1);
            MMA16816(d[1][0], ah[1], bh0); MMA16816(d[1][1], ah[1], bh1);
            MMA16816(d[0][0], al[0], bh0); MMA16816(d[0][1], al[0], bh1);
            MMA16816(d[1][0], al[1], bh0); MMA16816(d[1][1], al[1], bh1);
            MMA16816(d[0][0], ah[0], bl0); MMA16816(d[0][1], ah[0], bl1);
            MMA16816(d[1][0], ah[1], bl0); MMA16816(d[1][1], ah[1], bl1);
        }
    }

    // epilogue: D frag (m16n8): lane -> rows {l/4, l/4+8}, cols {2(l%4), +1}
    const int r0 = lane >> 2;
    const int cp = (lane & 3) * 2;
    const float bv[4] = { __ldg(bias + cp),     __ldg(bias + cp + 1),
                          __ldg(bias + cp + 8), __ldg(bias + cp + 9) };
    const int wsp = wpt & (THW - 1);
    float* __restrict__ ob = out + b * (NCO * THW) + wsp;
#pragma unroll
    for (int m = 0; m < 2; m++)
#pragma unroll
        for (int n = 0; n < 2; n++) {
            const int col = n * 8 + cp;
            const int row = 16 * m + r0;
            ob[(col)     * THW + row]     = d[m][n][0] + bv[n * 2 + 0];
            ob[(col + 1) * THW + row]     = d[m][n][1] + bv[n * 2 + 1];
            ob[(col)     * THW + row + 8] = d[m][n][2] + bv[n * 2 + 0];
            ob[(col + 1) * THW + row + 8] = d[m][n][3] + bv[n * 2 + 1];
        }
}

extern "C" void kernel_launch(void* const* d_in, const int* in_sizes, int n_in,
                              void* d_out, int out_size)
{
    const float* x    = (const float*)d_in[0];
    const float* temp = (const float*)d_in[1];
    const float* wgt  = (const float*)d_in[2];
    const float* bias = (const float*)d_in[3];
    float* out = (float*)d_out;

    transpose_x_kernel<<<(NB * NT * 4 * HW) / 256, 256>>>(x);
    prep_b_kernel<<<(NK * 2 * 2 * 32 + 255) / 256, 256>>>(wgt);
    deform_conv3d_mma_kernel<<<(NB * THW) / 256, 256>>>(temp, bias, out);
}